// round 10
// baseline (speedup 1.0000x reference)
#include <cuda_runtime.h>
#include <cuda_bf16.h>
#include <math.h>

// ---------------- constants ----------------
#define BATCH 16
#define GRID_ 4
#define NPATCH 16
#define PB 256            // BATCH * NPATCH
#define PSIZE 220
#define DIM 512
#define DEPTH 6
#define HEADS 8
#define DH 64
#define MLP_ 2048
#define NC 1000
#define NTOK 17           // NP + 1
#define ROWS 272          // BATCH * NTOK

// CNN stage dims
// conv1: 220 -> 107, pool -> 103
// conv2: 103 -> 49,  pool -> 45
// conv3: 45  -> 20,  pool -> 16

// ---------------- scratch (device globals; no allocation) ----------------
__device__ __align__(16) float g_A[93763584];   // max: conv1 out 256*32*107*107
__device__ __align__(16) float g_B[90259456];   // max: poolH1 out 256*32*107*103
__device__ __align__(16) float g_xproj[PB * DIM];
__device__ __align__(16) float g_x[ROWS * DIM];
__device__ __align__(16) float g_h[ROWS * DIM];
__device__ __align__(16) float g_qkv[ROWS * 3 * DIM];
__device__ __align__(16) float g_attn[ROWS * DIM];
__device__ __align__(16) float g_ff[ROWS * MLP_];
__device__ __align__(16) float g_cls[BATCH * DIM];

// ---------------- conv1: img patches -> [256,32,107,107], ReLU fused ----------------
__global__ void conv1_kernel(const float* __restrict__ img, const float* __restrict__ w,
                             float* __restrict__ out) {
    __shared__ __align__(16) float s_in[37 * 37];
    __shared__ __align__(16) float s_w[49 * 32];   // [tap][oc]
    int p = blockIdx.z;
    int b = p >> 4, gh = (p >> 2) & 3, gw = p & 3;
    int ty0 = blockIdx.y * 16, tx0 = blockIdx.x * 16;
    int tid = threadIdx.x;

    for (int i = tid; i < 49 * 32; i += 256) {
        int oc = i & 31, tap = i >> 5;
        s_w[i] = w[oc * 49 + tap];
    }
    int iy0 = ty0 * 2, ix0 = tx0 * 2;
    const float* ibase = img + (size_t)b * 880 * 880 + (size_t)(gh * PSIZE) * 880 + gw * PSIZE;
    for (int i = tid; i < 37 * 37; i += 256) {
        int r = i / 37, c = i % 37;
        int y = iy0 + r, x = ix0 + c;
        s_in[i] = (y < PSIZE && x < PSIZE) ? ibase[(size_t)y * 880 + x] : 0.f;
    }
    __syncthreads();

    int lty = tid >> 4, ltx = tid & 15;
    float acc[32];
#pragma unroll
    for (int i = 0; i < 32; i++) acc[i] = 0.f;
#pragma unroll
    for (int dy = 0; dy < 7; dy++) {
#pragma unroll
        for (int dx = 0; dx < 7; dx++) {
            float iv = s_in[(2 * lty + dy) * 37 + 2 * ltx + dx];
            const float4* w4 = (const float4*)&s_w[(dy * 7 + dx) * 32];
#pragma unroll
            for (int q = 0; q < 8; q++) {
                float4 wv = w4[q];
                acc[q * 4 + 0] += iv * wv.x;
                acc[q * 4 + 1] += iv * wv.y;
                acc[q * 4 + 2] += iv * wv.z;
                acc[q * 4 + 3] += iv * wv.w;
            }
        }
    }
    int oy = ty0 + lty, ox = tx0 + ltx;
    if (oy < 107 && ox < 107) {
        size_t obase = (size_t)p * 32 * 107 * 107 + (size_t)oy * 107 + ox;
#pragma unroll
        for (int oc = 0; oc < 32; oc++)
            out[obase + (size_t)oc * 107 * 107] = fmaxf(acc[oc], 0.f);
    }
}

// ---------------- conv2: [256,32,103,103] -> [256,64,49,49], ReLU fused ----------------
// grid (7 ytiles, 4 oc-groups, 256 patches), block 352 (343 active: 7x49 out tile)
__global__ void conv2_kernel(const float* __restrict__ in, const float* __restrict__ w,
                             float* __restrict__ out) {
    __shared__ __align__(16) float s_in[19 * 103];
    __shared__ __align__(16) float s_w[49 * 16];   // [tap][oc_local]
    int ytile = blockIdx.x, g = blockIdx.y, p = blockIdx.z;
    int tid = threadIdx.x;
    int ly = tid / 49, lx = tid % 49;
    bool active = tid < 343;
    float acc[16];
#pragma unroll
    for (int i = 0; i < 16; i++) acc[i] = 0.f;

    const float* inp = in + (size_t)p * 32 * 103 * 103 + (size_t)(ytile * 14) * 103;
    const float* wp = w + (size_t)g * 16 * 32 * 49;

    for (int ic = 0; ic < 32; ic++) {
        __syncthreads();
        for (int i = tid; i < 19 * 103; i += 352)
            s_in[i] = inp[(size_t)ic * 103 * 103 + i];
        for (int i = tid; i < 49 * 16; i += 352) {
            int tap = i >> 4, ol = i & 15;
            s_w[i] = wp[(size_t)(ol * 32 + ic) * 49 + tap];
        }
        __syncthreads();
        if (active) {
#pragma unroll
            for (int dy = 0; dy < 7; dy++) {
#pragma unroll
                for (int dx = 0; dx < 7; dx++) {
                    float iv = s_in[(2 * ly + dy) * 103 + 2 * lx + dx];
                    const float4* w4 = (const float4*)&s_w[(dy * 7 + dx) * 16];
#pragma unroll
                    for (int q = 0; q < 4; q++) {
                        float4 wv = w4[q];
                        acc[q * 4 + 0] += iv * wv.x;
                        acc[q * 4 + 1] += iv * wv.y;
                        acc[q * 4 + 2] += iv * wv.z;
                        acc[q * 4 + 3] += iv * wv.w;
                    }
                }
            }
        }
    }
    if (active) {
        int oy = ytile * 7 + ly;
        size_t obase = ((size_t)p * 64 + g * 16) * 49 * 49 + (size_t)oy * 49 + lx;
#pragma unroll
        for (int o = 0; o < 16; o++)
            out[obase + (size_t)o * 49 * 49] = fmaxf(acc[o], 0.f);   // ReLU
    }
}

// ---------------- conv3: [256,64,45,45] -> [256,64,20,20], ReLU fused ----------------
// grid (4 oc-groups, 256 patches), block 400 (20x20 out)
__global__ void conv3_kernel(const float* __restrict__ in, const float* __restrict__ w,
                             float* __restrict__ out) {
    __shared__ __align__(16) float s_in[45 * 45];
    __shared__ __align__(16) float s_w[49 * 16];
    int g = blockIdx.x, p = blockIdx.y;
    int tid = threadIdx.x;
    int ly = tid / 20, lx = tid % 20;
    float acc[16];
#pragma unroll
    for (int i = 0; i < 16; i++) acc[i] = 0.f;

    const float* inp = in + (size_t)p * 64 * 45 * 45;
    const float* wp = w + (size_t)g * 16 * 64 * 49;

    for (int ic = 0; ic < 64; ic++) {
        __syncthreads();
        for (int i = tid; i < 45 * 45; i += 400)
            s_in[i] = inp[(size_t)ic * 45 * 45 + i];
        for (int i = tid; i < 49 * 16; i += 400) {
            int tap = i >> 4, ol = i & 15;
            s_w[i] = wp[(size_t)(ol * 64 + ic) * 49 + tap];
        }
        __syncthreads();
#pragma unroll
        for (int dy = 0; dy < 7; dy++) {
#pragma unroll
            for (int dx = 0; dx < 7; dx++) {
                float iv = s_in[(2 * ly + dy) * 45 + 2 * lx + dx];
                const float4* w4 = (const float4*)&s_w[(dy * 7 + dx) * 16];
#pragma unroll
                for (int q = 0; q < 4; q++) {
                    float4 wv = w4[q];
                    acc[q * 4 + 0] += iv * wv.x;
                    acc[q * 4 + 1] += iv * wv.y;
                    acc[q * 4 + 2] += iv * wv.z;
                    acc[q * 4 + 3] += iv * wv.w;
                }
            }
        }
    }
    size_t obase = ((size_t)p * 64 + g * 16) * 400 + (size_t)ly * 20 + lx;
#pragma unroll
    for (int o = 0; o < 16; o++)
        out[obase + (size_t)o * 400] = fmaxf(acc[o], 0.f);           // ReLU
}

// ---------------- separable maxpool 7x7 s1 p1 ----------------
__global__ void poolH_kernel(const float* __restrict__ in, float* __restrict__ out,
                             int planes, int H, int W) {
    int Wo = W - 4;
    long total = (long)planes * H * Wo;
    long idx = (long)blockIdx.x * 256 + threadIdx.x;
    if (idx >= total) return;
    int ox = (int)(idx % Wo);
    long rest = idx / Wo;
    int y = (int)(rest % H);
    long pl = rest / H;
    const float* row = in + ((long)pl * H + y) * W;
    float m = -1e30f;
#pragma unroll
    for (int k = 0; k < 7; k++) {
        int x = ox - 1 + k;
        if (x >= 0 && x < W) m = fmaxf(m, row[x]);
    }
    out[idx] = m;
}

__global__ void poolV_kernel(const float* __restrict__ in, float* __restrict__ out,
                             int planes, int H, int W) {
    int Ho = H - 4;
    long total = (long)planes * Ho * W;
    long idx = (long)blockIdx.x * 256 + threadIdx.x;
    if (idx >= total) return;
    int x = (int)(idx % W);
    long rest = idx / W;
    int oy = (int)(rest % Ho);
    long pl = rest / Ho;
    const float* base = in + (long)pl * H * W;
    float m = -1e30f;
#pragma unroll
    for (int k = 0; k < 7; k++) {
        int r = oy - 1 + k;
        if (r >= 0 && r < H) m = fmaxf(m, base[(long)r * W + x]);
    }
    out[idx] = m;
}

// ---------------- generic fp32 GEMM: C[M,N] = A[M,K] @ W[K,N] (+epilogue) --------
// mode 0: (+bias)   mode 1: +bias +resid   mode 2: +bias, GELU   mode 3: atomicAdd (split-K)
__device__ __forceinline__ float gelu_exact(float v) {
    return 0.5f * v * (1.0f + erff(v * 0.70710678118654752440f));
}

__global__ void gemm_kernel(const float* __restrict__ A, const float* __restrict__ W,
                            const float* __restrict__ bias, const float* resid,
                            float* C, int M, int N, int K, int mode) {
    __shared__ __align__(16) float As[16][65];
    __shared__ __align__(16) float Ws[16][64];
    int tid = threadIdx.x;
    int tx = tid & 15, ty = tid >> 4;
    int n0 = blockIdx.x * 64, m0 = blockIdx.y * 64;
    int kpb = K / gridDim.z;
    int kbeg = blockIdx.z * kpb, kend = kbeg + kpb;

    float acc[4][4];
#pragma unroll
    for (int i = 0; i < 4; i++)
#pragma unroll
        for (int j = 0; j < 4; j++) acc[i][j] = 0.f;

    int a_m = tid >> 2, a_k4 = (tid & 3) * 4;
    int w_k = tid >> 4, w_n4 = (tid & 15) * 4;

    for (int k0 = kbeg; k0 < kend; k0 += 16) {
        float4 av = make_float4(0.f, 0.f, 0.f, 0.f);
        if (m0 + a_m < M)
            av = *(const float4*)(A + (size_t)(m0 + a_m) * K + k0 + a_k4);
        As[a_k4 + 0][a_m] = av.x;
        As[a_k4 + 1][a_m] = av.y;
        As[a_k4 + 2][a_m] = av.z;
        As[a_k4 + 3][a_m] = av.w;
        *(float4*)&Ws[w_k][w_n4] = *(const float4*)(W + (size_t)(k0 + w_k) * N + n0 + w_n4);
        __syncthreads();
#pragma unroll
        for (int kk = 0; kk < 16; kk++) {
            float4 bv = *(const float4*)&Ws[kk][tx * 4];
            float a0 = As[kk][ty * 4 + 0];
            float a1 = As[kk][ty * 4 + 1];
            float a2 = As[kk][ty * 4 + 2];
            float a3 = As[kk][ty * 4 + 3];
            acc[0][0] += a0 * bv.x; acc[0][1] += a0 * bv.y; acc[0][2] += a0 * bv.z; acc[0][3] += a0 * bv.w;
            acc[1][0] += a1 * bv.x; acc[1][1] += a1 * bv.y; acc[1][2] += a1 * bv.z; acc[1][3] += a1 * bv.w;
            acc[2][0] += a2 * bv.x; acc[2][1] += a2 * bv.y; acc[2][2] += a2 * bv.z; acc[2][3] += a2 * bv.w;
            acc[3][0] += a3 * bv.x; acc[3][1] += a3 * bv.y; acc[3][2] += a3 * bv.z; acc[3][3] += a3 * bv.w;
        }
        __syncthreads();
    }

#pragma unroll
    for (int i = 0; i < 4; i++) {
        int m = m0 + ty * 4 + i;
        if (m >= M) continue;
#pragma unroll
        for (int j = 0; j < 4; j++) {
            int n = n0 + tx * 4 + j;
            float v = acc[i][j];
            if (mode == 3) {
                atomicAdd(&C[(size_t)m * N + n], v);
            } else {
                if (bias) v += bias[n];
                if (mode == 2) v = gelu_exact(v);
                if (mode == 1) v += resid[(size_t)m * N + n];
                C[(size_t)m * N + n] = v;
            }
        }
    }
}

// ---------------- layernorm (width 512) ----------------
__global__ void ln_kernel(const float* __restrict__ in, int row_stride,
                          const float* __restrict__ g, const float* __restrict__ b,
                          float* __restrict__ out) {
    int r = blockIdx.x;
    const float* x = in + (size_t)r * row_stride;
    int tid = threadIdx.x;  // 128
    float4 v = *(const float4*)(x + tid * 4);
    float s = v.x + v.y + v.z + v.w;
    float ss = v.x * v.x + v.y * v.y + v.z * v.z + v.w * v.w;
    __shared__ float rs[4], rss[4];
#pragma unroll
    for (int o = 16; o > 0; o >>= 1) {
        s += __shfl_down_sync(0xffffffffu, s, o);
        ss += __shfl_down_sync(0xffffffffu, ss, o);
    }
    int lane = tid & 31, wp = tid >> 5;
    if (lane == 0) { rs[wp] = s; rss[wp] = ss; }
    __syncthreads();
    float S = rs[0] + rs[1] + rs[2] + rs[3];
    float SS = rss[0] + rss[1] + rss[2] + rss[3];
    float mean = S * (1.f / 512.f);
    float var = SS * (1.f / 512.f) - mean * mean;
    float inv = rsqrtf(var + 1e-5f);
    float4 gv = *(const float4*)(g + tid * 4);
    float4 bv = *(const float4*)(b + tid * 4);
    float4 o;
    o.x = (v.x - mean) * inv * gv.x + bv.x;
    o.y = (v.y - mean) * inv * gv.y + bv.y;
    o.z = (v.z - mean) * inv * gv.z + bv.z;
    o.w = (v.w - mean) * inv * gv.w + bv.w;
    *(float4*)(out + (size_t)r * 512 + tid * 4) = o;
}

// ---------------- attention: per (head, batch) block ----------------
__global__ void attn_kernel(const float* __restrict__ qkv, float* __restrict__ attnout) {
    int h = blockIdx.x, b = blockIdx.y;
    __shared__ float sq[17][65], sk[17][65], sv[17][65], sp[17][18];
    int tid = threadIdx.x;  // 128
    for (int idx = tid; idx < 17 * 64; idx += 128) {
        int n = idx >> 6, d = idx & 63;
        const float* row = qkv + (size_t)(b * 17 + n) * 1536 + h * 64 + d;
        sq[n][d] = row[0];
        sk[n][d] = row[512];
        sv[n][d] = row[1024];
    }
    __syncthreads();
    for (int idx = tid; idx < 289; idx += 128) {
        int qi = idx / 17, ki = idx % 17;
        float s = 0.f;
#pragma unroll
        for (int d = 0; d < 64; d++) s += sq[qi][d] * sk[ki][d];
        sp[qi][ki] = s * 0.125f;
    }
    __syncthreads();
    if (tid < 17) {
        float m = -1e30f;
        for (int k = 0; k < 17; k++) m = fmaxf(m, sp[tid][k]);
        float sum = 0.f;
        for (int k = 0; k < 17; k++) { float e = expf(sp[tid][k] - m); sp[tid][k] = e; sum += e; }
        float inv = 1.f / sum;
        for (int k = 0; k < 17; k++) sp[tid][k] *= inv;
    }
    __syncthreads();
    for (int idx = tid; idx < 17 * 64; idx += 128) {
        int n = idx >> 6, d = idx & 63;
        float o = 0.f;
#pragma unroll
        for (int k = 0; k < 17; k++) o += sp[n][k] * sv[k][d];
        attnout[(size_t)(b * 17 + n) * 512 + h * 64 + d] = o;
    }
}

// ---------------- assemble tokens ----------------
__global__ void assemble_kernel(const float* __restrict__ xproj, const float* __restrict__ flat_b,
                                const float* __restrict__ cls_token, const float* __restrict__ pos_emb,
                                float* __restrict__ x) {
    int idx = blockIdx.x * 256 + threadIdx.x;
    if (idx >= BATCH * NTOK * DIM) return;
    int d = idx & 511;
    int r = (idx >> 9) % NTOK;
    int b = idx / (NTOK * DIM);
    float v;
    if (r == 0)
        v = cls_token[d] + pos_emb[d];
    else
        v = xproj[(size_t)(b * NPATCH + (r - 1)) * DIM + d] + flat_b[d] + pos_emb[r * DIM + d];
    x[idx] = v;
}

__global__ void zero_kernel(float* p, int n) {
    int i = blockIdx.x * 256 + threadIdx.x;
    if (i < n) p[i] = 0.f;
}

// ---------------- head ----------------
__global__ void head_kernel(const float* __restrict__ cls, const float* __restrict__ hw,
                            const float* __restrict__ hb, float* __restrict__ out) {
    int b = blockIdx.x;
    __shared__ float s[512];
    int tid = threadIdx.x;  // 256
    s[tid] = cls[(size_t)b * 512 + tid];
    s[tid + 256] = cls[(size_t)b * 512 + tid + 256];
    __syncthreads();
    for (int c = tid; c < NC; c += 256) {
        float acc = hb[c];
        for (int k = 0; k < 512; k++) acc += s[k] * hw[(size_t)k * NC + c];
        out[(size_t)b * NC + c] = acc;
    }
}

// ---------------- launch ----------------
static inline int cdiv_l(long a, int b) { return (int)((a + b - 1) / b); }

extern "C" void kernel_launch(void* const* d_in, const int* in_sizes, int n_in,
                              void* d_out, int out_size) {
    const float* img      = (const float*)d_in[0];
    const float* conv1_w  = (const float*)d_in[1];
    const float* conv2_w  = (const float*)d_in[2];
    const float* conv3_w  = (const float*)d_in[3];
    const float* flat_w   = (const float*)d_in[4];
    const float* flat_b   = (const float*)d_in[5];
    const float* cls_tok  = (const float*)d_in[6];
    const float* pos_emb  = (const float*)d_in[7];
    const float* ln1_g    = (const float*)d_in[8];
    const float* ln1_b    = (const float*)d_in[9];
    const float* qkv_w    = (const float*)d_in[10];
    const float* out_w    = (const float*)d_in[11];
    const float* out_b    = (const float*)d_in[12];
    const float* ln2_g    = (const float*)d_in[13];
    const float* ln2_b    = (const float*)d_in[14];
    const float* ff1_w    = (const float*)d_in[15];
    const float* ff1_b    = (const float*)d_in[16];
    const float* ff2_w    = (const float*)d_in[17];
    const float* ff2_b    = (const float*)d_in[18];
    const float* hln_g    = (const float*)d_in[19];
    const float* hln_b    = (const float*)d_in[20];
    const float* head_w   = (const float*)d_in[21];
    const float* head_b   = (const float*)d_in[22];
    float* outp = (float*)d_out;

    float *A, *Bb, *xproj, *x, *h, *qkv, *attn, *ff, *cls;
    cudaGetSymbolAddress((void**)&A, g_A);
    cudaGetSymbolAddress((void**)&Bb, g_B);
    cudaGetSymbolAddress((void**)&xproj, g_xproj);
    cudaGetSymbolAddress((void**)&x, g_x);
    cudaGetSymbolAddress((void**)&h, g_h);
    cudaGetSymbolAddress((void**)&qkv, g_qkv);
    cudaGetSymbolAddress((void**)&attn, g_attn);
    cudaGetSymbolAddress((void**)&ff, g_ff);
    cudaGetSymbolAddress((void**)&cls, g_cls);

    // --- CNN stage 1 ---
    conv1_kernel<<<dim3(7, 7, PB), 256>>>(img, conv1_w, A);
    {
        long t = (long)PB * 32 * 107 * 103;
        poolH_kernel<<<cdiv_l(t, 256), 256>>>(A, Bb, PB * 32, 107, 107);
        t = (long)PB * 32 * 103 * 103;
        poolV_kernel<<<cdiv_l(t, 256), 256>>>(Bb, A, PB * 32, 107, 103);
    }
    // --- CNN stage 2 ---
    conv2_kernel<<<dim3(7, 4, PB), 352>>>(A, conv2_w, Bb);
    {
        long t = (long)PB * 64 * 49 * 45;
        poolH_kernel<<<cdiv_l(t, 256), 256>>>(Bb, A, PB * 64, 49, 49);
        t = (long)PB * 64 * 45 * 45;
        poolV_kernel<<<cdiv_l(t, 256), 256>>>(A, Bb, PB * 64, 49, 45);
    }
    // --- CNN stage 3 ---
    conv3_kernel<<<dim3(4, PB), 400>>>(Bb, conv3_w, A);
    {
        long t = (long)PB * 64 * 20 * 16;
        poolH_kernel<<<cdiv_l(t, 256), 256>>>(A, Bb, PB * 64, 20, 20);
        t = (long)PB * 64 * 16 * 16;
        poolV_kernel<<<cdiv_l(t, 256), 256>>>(Bb, A, PB * 64, 20, 16);
    }
    // feat = A : [256, 16384]

    // --- flat projection (split-K=8, atomic) ---
    zero_kernel<<<cdiv_l(PB * DIM, 256), 256>>>(xproj, PB * DIM);
    gemm_kernel<<<dim3(DIM / 64, PB / 64, 8), 256>>>(A, flat_w, nullptr, nullptr, xproj,
                                                     PB, DIM, 16384, 3);
    assemble_kernel<<<cdiv_l(BATCH * NTOK * DIM, 256), 256>>>(xproj, flat_b, cls_tok, pos_emb, x);

    // --- transformer ---
    for (int l = 0; l < DEPTH; l++) {
        const float* qw = qkv_w + (size_t)l * DIM * 3 * DIM;
        const float* ow = out_w + (size_t)l * DIM * DIM;
        const float* ob = out_b + (size_t)l * DIM;
        const float* w1 = ff1_w + (size_t)l * DIM * MLP_;
        const float* b1 = ff1_b + (size_t)l * MLP_;
        const float* w2 = ff2_w + (size_t)l * MLP_ * DIM;
        const float* b2 = ff2_b + (size_t)l * DIM;

        ln_kernel<<<ROWS, 128>>>(x, DIM, ln1_g + l * DIM, ln1_b + l * DIM, h);
        gemm_kernel<<<dim3(1536 / 64, 5, 1), 256>>>(h, qw, nullptr, nullptr, qkv,
                                                    ROWS, 1536, DIM, 0);
        attn_kernel<<<dim3(HEADS, BATCH), 128>>>(qkv, attn);
        gemm_kernel<<<dim3(DIM / 64, 5, 1), 256>>>(attn, ow, ob, x, x,
                                                   ROWS, DIM, DIM, 1);
        ln_kernel<<<ROWS, 128>>>(x, DIM, ln2_g + l * DIM, ln2_b + l * DIM, h);
        gemm_kernel<<<dim3(MLP_ / 64, 5, 1), 256>>>(h, w1, b1, nullptr, ff,
                                                    ROWS, MLP_, DIM, 2);
        gemm_kernel<<<dim3(DIM / 64, 5, 1), 256>>>(ff, w2, b2, x, x,
                                                   ROWS, DIM, MLP_, 1);
    }

    // --- head ---
    ln_kernel<<<BATCH, 128>>>(x, NTOK * DIM, hln_g, hln_b, cls);
    head_kernel<<<BATCH, 256>>>(cls, head_w, head_b, outp);
}